// round 14
// baseline (speedup 1.0000x reference)
#include <cuda_runtime.h>
#include <cstddef>
#include <cstdint>

#define TLEN 512
#define NB   64
#define UDIM 256
#define GDIM 768
#define EDIM 300
#define CDIM 20
#define KP   260   // rk smem row pad: lane stride 1040B -> conflict-free LDS.128

__device__ float g_xw[(size_t)2 * NB * TLEN * GDIM];   // [dir][b*T+t][g]
__device__ float g_h1[(size_t)NB * TLEN * 2 * UDIM];   // [b*T+t][2U]
__device__ float g_hbuf[2 * 2 * 8 * 8 * UDIM];         // [par][dir][bg][8][U]
__device__ float g_h2[NB * 2 * UDIM];
__device__ unsigned g_cnt[4096];                       // 2 banks x 16 groups x 8 CTA x 2 bq x 8 pad

__device__ __forceinline__ unsigned long long ffma2(unsigned long long a,
                                                    unsigned long long b,
                                                    unsigned long long c) {
    unsigned long long d;
    asm("fma.rn.f32x2 %0,%1,%2,%3;" : "=l"(d) : "l"(a), "l"(b), "l"(c));
    return d;
}
__device__ __forceinline__ unsigned long long dup2(float x) {
    unsigned long long d;
    asm("mov.b64 %0,{%1,%1};" : "=l"(d) : "r"(__float_as_uint(x)));
    return d;
}
union F4U { float4 v; float f[4]; unsigned long long u[2]; };

__device__ __forceinline__ void st_release_gpu(unsigned* p, unsigned v) {
    asm volatile("st.release.gpu.global.u32 [%0], %1;" :: "l"(p), "r"(v) : "memory");
}
__device__ __forceinline__ unsigned ld_acquire_gpu(const unsigned* p) {
    unsigned v;
    asm volatile("ld.acquire.gpu.global.u32 %0, [%1];" : "=r"(v) : "l"(p) : "memory");
    return v;
}

// inf-safe fast activations (MUFU ex2/rcp based)
__device__ __forceinline__ float fsig(float x) {
    return __fdividef(1.0f, 1.0f + __expf(-x));
}
__device__ __forceinline__ float ftanh(float x) {
    return 1.0f - __fdividef(2.0f, 1.0f + __expf(2.0f * x));
}

// ================= GEMM: 2-stage register-prefetch pipeline =================
#define BM 128
#define BN 128
#define BK 8

__global__ __launch_bounds__(256, 2)
void gemm_kernel(int mode, const int* __restrict__ gidx, const float* __restrict__ emb,
                 const float* __restrict__ Wf, const float* __restrict__ Wb,
                 const float* __restrict__ bf, const float* __restrict__ bb,
                 int K, int czoff)
{
    const int tid = threadIdx.x;
    if (blockIdx.x == 0 && blockIdx.y == 0 && blockIdx.z == 0) {   // reset rec flag bank
        for (int i = tid; i < 2048; i += 256) g_cnt[czoff + i] = 0u;
    }
    const int dir = blockIdx.z;
    const float* __restrict__ W    = dir ? Wb : Wf;
    const float* __restrict__ bias = dir ? bb : bf;
    float* outp = g_xw + (size_t)dir * NB * TLEN * GDIM;
    const int bm = blockIdx.y * BM, bn = blockIdx.x * BN;

    __shared__ float As[BK][BM + 4];
    __shared__ float Bs[BK][BN];

    const int a_m = tid >> 1, a_k = (tid & 1) * 4;
    const int b_k = tid >> 5, b_n = (tid & 31) * 4;
    const int tx = tid & 15, ty = tid >> 4;

    const float* arow = mode ? (g_h1 + (size_t)(bm + a_m) * (2 * UDIM))
                             : (emb + (size_t)gidx[bm + a_m] * EDIM);

    auto loadA = [&](int k0, F4U& a) {
        if (k0 + a_k + 4 <= K) {
            a.v = *(const float4*)(arow + k0 + a_k);
        } else {
#pragma unroll
            for (int i = 0; i < 4; i++) {
                int kk = k0 + a_k + i;
                a.f[i] = (kk < K) ? arow[kk] : 0.0f;
            }
        }
    };
    auto loadB = [&](int k0, F4U& b) {
        int kk = k0 + b_k;
        b.v = make_float4(0.f, 0.f, 0.f, 0.f);
        if (kk < K) b.v = *(const float4*)(W + (size_t)kk * GDIM + bn + b_n);
    };
    auto stsTile = [&](const F4U& a, const F4U& b) {
        As[a_k + 0][a_m] = a.f[0]; As[a_k + 1][a_m] = a.f[1];
        As[a_k + 2][a_m] = a.f[2]; As[a_k + 3][a_m] = a.f[3];
        *(float4*)&Bs[b_k][b_n] = b.v;
    };

    unsigned long long acc[8][4];
#pragma unroll
    for (int i = 0; i < 8; i++)
#pragma unroll
        for (int j = 0; j < 4; j++) acc[i][j] = 0ull;

    {
        F4U a0, b0;
        loadA(0, a0); loadB(0, b0);
        stsTile(a0, b0);
    }
    __syncthreads();

    int k0 = 0;
    for (;;) {
        const int k1 = k0 + BK;
        const bool more = (k1 < K);
        F4U anx, bnx;
        if (more) { loadA(k1, anx); loadB(k1, bnx); }   // prefetch next (hidden)

#pragma unroll
        for (int kk = 0; kk < BK; kk++) {
            F4U a0, a1, b0, b1;
            a0.v = *(const float4*)&As[kk][ty * 4];
            a1.v = *(const float4*)&As[kk][64 + ty * 4];
            b0.v = *(const float4*)&Bs[kk][tx * 4];
            b1.v = *(const float4*)&Bs[kk][64 + tx * 4];
            unsigned long long ap[8];
            unsigned long long bp[4] = { b0.u[0], b0.u[1], b1.u[0], b1.u[1] };
#pragma unroll
            for (int i = 0; i < 4; i++) { ap[i] = dup2(a0.f[i]); ap[4 + i] = dup2(a1.f[i]); }
#pragma unroll
            for (int i = 0; i < 8; i++)
#pragma unroll
                for (int j = 0; j < 4; j++)
                    acc[i][j] = ffma2(ap[i], bp[j], acc[i][j]);
        }
        if (!more) break;
        __syncthreads();
        stsTile(anx, bnx);
        __syncthreads();
        k0 = k1;
    }

#pragma unroll
    for (int i = 0; i < 8; i++) {
        int m = bm + ((i < 4) ? (ty * 4 + i) : (64 + ty * 4 + i - 4));
        float* orow = outp + (size_t)m * GDIM + bn;
#pragma unroll
        for (int j = 0; j < 4; j++) {
            int c = (j < 2) ? (tx * 4 + j * 2) : (64 + tx * 4 + (j - 2) * 2);
            F4U t; t.u[0] = acc[i][j];
            float2 r;
            r.x = t.f[0] + bias[bn + c];
            r.y = t.f[1] + bias[bn + c + 1];
            *(float2*)(orow + c) = r;
        }
    }
}

// ===== Recurrence v5: pairwise producer flags, per-warp quadrant reload =====
// 128 CTAs = dir(2) x batch-group(8) x unit-slice(8).
// 256 threads = kq(4) x bq(2) x j(32). Warp (kq,bq) consumes h units
// [64kq,64kq+64) of batches bq*4..bq*4+3 -> produced by CTAs {2kq,2kq+1},
// batch-half bq. Flags: one per (CTA, bq), value = steps published.
// Per step: [poll 2 flags, ldcg own quadrant, syncwarp] matvec -> partials ->
// BAR1 -> kq0: reduce+gates(hprev regs)+STG+syncwarp+st.release flag -> BAR2.
#define RED_F (3 * 2 * 32 * 12)
#define REC_SMEM ((96 * KP + 8 * 256 + RED_F) * 4)

__global__ __launch_bounds__(256, 1)
void rec_kernel(const float* __restrict__ rkf, const float* __restrict__ rkb,
                const float* __restrict__ rbf, const float* __restrict__ rbb,
                int layer, int coff)
{
    extern __shared__ float sm[];
    float* rk_s = sm;                       // [96][KP]
    float* h_s  = sm + 96 * KP;             // [8][256]
    float* red  = h_s + 8 * 256;            // [3][2][32][12]
    const int blk = blockIdx.x, dir = blk >> 6, bg = (blk >> 3) & 7, us = blk & 7;
    const int tid = threadIdx.x;
    const int kq = tid >> 6, bq = (tid >> 5) & 1, j = tid & 31;
    const float* __restrict__ rk = dir ? rkb : rkf;
    const float* __restrict__ rb = dir ? rbb : rbf;

    for (int i = tid; i < 96 * 256; i += 256) {
        int k = i / 96, c = i - k * 96;
        rk_s[c * KP + k] = rk[(size_t)k * GDIM + (c >> 5) * UDIM + us * 32 + (c & 31)];
    }
    for (int i = tid; i < 8 * 256; i += 256) h_s[i] = 0.0f;
    __syncthreads();

    const int u = us * 32 + j;
    const int kb = kq * 64;
    const float rbz = rb[u], rbr = rb[UDIM + u], rbh = rb[2 * UDIM + u];
    const float* xwd = g_xw + (size_t)dir * NB * TLEN * GDIM;
    unsigned* fbase = g_cnt + coff + (dir * 8 + bg) * 128;   // 8 CTA x 2 bq x 8 pad
    unsigned* fl0 = fbase + ((2 * kq)     * 2 + bq) * 8;     // producer flags I consume
    unsigned* fl1 = fbase + ((2 * kq + 1) * 2 + bq) * 8;
    unsigned* flmy = fbase + (us * 2 + bq) * 8;              // flag I publish (kq0 warps)
    const float* rzp = rk_s + (size_t)j * KP + kb;
    const float* rrp = rk_s + (size_t)(32 + j) * KP + kb;
    const float* rhp = rk_s + (size_t)(64 + j) * KP + kb;
    const float* hpb = h_s + (bq * 4) * 256 + kb;

    // per-warp quadrant float4 indices (same layout in h_s and group g_hbuf)
    const int qi0 = (bq * 4 + (j >> 4)) * 64 + kq * 16 + (j & 15);
    const int qi1 = qi0 + 2 * 64;            // batches +2

    float hprev[4] = {0.f, 0.f, 0.f, 0.f};   // kq0 warps: own-unit h state

    const size_t grp = (size_t)(dir * 8 + bg) * (8 * UDIM);
    float* gb_par[2] = { g_hbuf + (0 * 2 + dir) * 8 * UDIM + (size_t)(bg) * 0 + ((0 * 2 + dir) * 8 + bg) * 0,  // placeholder init below
                         nullptr };
    // (compute cleanly:)
    float* gb0 = g_hbuf + ((0 * 2 + dir) * 8 + bg) * (8 * UDIM);
    float* gb1 = g_hbuf + ((1 * 2 + dir) * 8 + bg) * (8 * UDIM);
    (void)grp; (void)gb_par;

    for (int s = 0; s < TLEN; s++) {
        const int t = dir ? (TLEN - 1 - s) : s;

        float xz[4], xr[4], xh[4];
        if (kq == 0) {                       // x prefetch first: overlaps flag wait
#pragma unroll
            for (int i = 0; i < 4; i++) {
                const float* xr0 = xwd + ((size_t)(bg * 8 + bq * 4 + i) * TLEN + t) * GDIM;
                xz[i] = __ldg(xr0 + u);
                xr[i] = __ldg(xr0 + UDIM + u);
                xh[i] = __ldg(xr0 + 2 * UDIM + u);
            }
        }

        if (s > 0) {
            if (j == 0) {
                const unsigned tgt = (unsigned)s;
                while (ld_acquire_gpu(fl0) < tgt) __nanosleep(32);
                while (ld_acquire_gpu(fl1) < tgt) __nanosleep(32);
            }
            __syncwarp();
            const float4* src = (const float4*)(((s & 1) ? gb0 : gb1));  // parity (s-1)&1
            float4* dst = (float4*)h_s;
            dst[qi0] = __ldcg(src + qi0);
            dst[qi1] = __ldcg(src + qi1);
            __syncwarp();
        }

        unsigned long long az[4], ar[4], ah[4];
#pragma unroll
        for (int i = 0; i < 4; i++) { az[i] = 0ull; ar[i] = 0ull; ah[i] = 0ull; }

#pragma unroll 4
        for (int k = 0; k < 64; k += 4) {
            F4U vz, vr, vh;
            vz.v = *(const float4*)(rzp + k);
            vr.v = *(const float4*)(rrp + k);
            vh.v = *(const float4*)(rhp + k);
#pragma unroll
            for (int i = 0; i < 4; i++) {
                F4U hv; hv.v = *(const float4*)(hpb + i * 256 + k);
                az[i] = ffma2(vz.u[0], hv.u[0], az[i]);
                az[i] = ffma2(vz.u[1], hv.u[1], az[i]);
                ar[i] = ffma2(vr.u[0], hv.u[0], ar[i]);
                ar[i] = ffma2(vr.u[1], hv.u[1], ar[i]);
                ah[i] = ffma2(vh.u[0], hv.u[0], ah[i]);
                ah[i] = ffma2(vh.u[1], hv.u[1], ah[i]);
            }
        }

        float sz[4], sr[4], sh[4];
#pragma unroll
        for (int i = 0; i < 4; i++) {
            F4U a; a.u[0] = az[i]; sz[i] = a.f[0] + a.f[1];
            a.u[0] = ar[i];        sr[i] = a.f[0] + a.f[1];
            a.u[0] = ah[i];        sh[i] = a.f[0] + a.f[1];
        }

        if (kq != 0) {
            float* rp = red + (((kq - 1) * 2 + bq) * 32 + j) * 12;
            *(float4*)(rp + 0) = make_float4(sz[0], sz[1], sz[2], sz[3]);
            *(float4*)(rp + 4) = make_float4(sr[0], sr[1], sr[2], sr[3]);
            *(float4*)(rp + 8) = make_float4(sh[0], sh[1], sh[2], sh[3]);
        }
        __syncthreads();   // BAR1: partials visible to kq0

        if (kq == 0) {
#pragma unroll
            for (int q = 0; q < 3; q++) {
                const float* rp = red + ((q * 2 + bq) * 32 + j) * 12;
                float4 a = *(const float4*)(rp + 0);
                float4 b = *(const float4*)(rp + 4);
                float4 c = *(const float4*)(rp + 8);
                sz[0] += a.x; sz[1] += a.y; sz[2] += a.z; sz[3] += a.w;
                sr[0] += b.x; sr[1] += b.y; sr[2] += b.z; sr[3] += b.w;
                sh[0] += c.x; sh[1] += c.y; sh[2] += c.z; sh[3] += c.w;
            }
            float* gb = (s & 1) ? gb1 : gb0;          // publish parity s&1
            float hn[4];
#pragma unroll
            for (int i = 0; i < 4; i++) {
                const int bL = bq * 4 + i;
                float z = fsig(xz[i] + rbz + sz[i]);
                float r = fsig(xr[i] + rbr + sr[i]);
                float hh = ftanh(xh[i] + rbh + r * sh[i]);
                hn[i] = z * hprev[i] + (1.f - z) * hh;
                hprev[i] = hn[i];
                gb[bL * UDIM + u] = hn[i];
            }
            __syncwarp();                              // warp STGs ordered
            if (j == 0) st_release_gpu(flmy, (unsigned)(s + 1));
            // off-path global stores (read only by later launches)
            if (layer == 1) {
#pragma unroll
                for (int i = 0; i < 4; i++) {
                    const int Bg = bg * 8 + bq * 4 + i;
                    g_h1[((size_t)Bg * TLEN + t) * (2 * UDIM) + dir * UDIM + u] = hn[i];
                }
            } else if (s == TLEN - 1) {
#pragma unroll
                for (int i = 0; i < 4; i++) {
                    const int Bg = bg * 8 + bq * 4 + i;
                    g_h2[Bg * 2 * UDIM + dir * UDIM + u] = hn[i];
                }
            }
        }
        __syncthreads();   // BAR2: red safe to overwrite next step
    }
}

// ======================== softmax head =================================
__global__ void out_kernel(const float* __restrict__ wout, const float* __restrict__ bout,
                           float* __restrict__ out)
{
    __shared__ float h[2 * UDIM];
    const int b = blockIdx.x, t = threadIdx.x;
    for (int i = t; i < 128; i += 32)
        ((float4*)h)[i] = ((const float4*)(g_h2 + b * 2 * UDIM))[i];
    __syncwarp();
    float l = -1e30f;
    if (t < CDIM) {
        float a = bout[t];
        for (int k = 0; k < 2 * UDIM; k++) a = fmaf(h[k], wout[k * CDIM + t], a);
        l = a;
    }
    float m = l;
    for (int o = 16; o; o >>= 1) m = fmaxf(m, __shfl_xor_sync(~0u, m, o));
    float e = (t < CDIM) ? expf(l - m) : 0.0f, ssum = e;
    for (int o = 16; o; o >>= 1) ssum += __shfl_xor_sync(~0u, ssum, o);
    if (t < CDIM) out[b * CDIM + t] = e / ssum;
}

// ========================= launcher ====================================
extern "C" void kernel_launch(void* const* d_in, const int* in_sizes, int n_in,
                              void* d_out, int out_size)
{
    const int*   x    = (const int*)d_in[0];
    const float* emb  = (const float*)d_in[1];
    const float* k1f  = (const float*)d_in[2];
    const float* rk1f = (const float*)d_in[3];
    const float* b1f  = (const float*)d_in[4];
    const float* k1b  = (const float*)d_in[5];
    const float* rk1b = (const float*)d_in[6];
    const float* b1b  = (const float*)d_in[7];
    const float* k2f  = (const float*)d_in[8];
    const float* rk2f = (const float*)d_in[9];
    const float* b2f  = (const float*)d_in[10];
    const float* k2b  = (const float*)d_in[11];
    const float* rk2b = (const float*)d_in[12];
    const float* b2b  = (const float*)d_in[13];
    const float* wout = (const float*)d_in[14];
    const float* bout = (const float*)d_in[15];
    float* out = (float*)d_out;
    (void)in_sizes; (void)n_in; (void)out_size;

    cudaFuncSetAttribute(rec_kernel, cudaFuncAttributeMaxDynamicSharedMemorySize, REC_SMEM);

    dim3 gg(GDIM / BN, (NB * TLEN) / BM, 2);
    gemm_kernel<<<gg, 256>>>(0, x, emb, k1f, k1b, b1f, b1b, EDIM, 0);
    rec_kernel<<<128, 256, REC_SMEM>>>(rk1f, rk1b, b1f + GDIM, b1b + GDIM, 1, 0);
    gemm_kernel<<<gg, 256>>>(1, x, emb, k2f, k2b, b2f, b2b, 2 * UDIM, 2048);
    rec_kernel<<<128, 256, REC_SMEM>>>(rk2f, rk2b, b2f + GDIM, b2b + GDIM, 2, 2048);
    out_kernel<<<NB, 32>>>(wout, bout, out);
}

// round 15
// speedup vs baseline: 1.2356x; 1.2356x over previous
#include <cuda_runtime.h>
#include <cstddef>
#include <cstdint>

#define TLEN 512
#define NB   64
#define UDIM 256
#define GDIM 768
#define EDIM 300
#define CDIM 20
#define KP   260   // rk smem row pad: lane stride 1040B -> conflict-free LDS.128

__device__ float g_xw[(size_t)2 * NB * TLEN * GDIM];   // [dir][b*T+t][g]
__device__ float g_h1[(size_t)NB * TLEN * 2 * UDIM];   // [b*T+t][2U]
__device__ float g_hbuf[2 * 2 * 8 * 8 * UDIM];         // [par][dir][bg][8][U]
__device__ float g_h2[NB * 2 * UDIM];
__device__ unsigned g_cnt[1024];                       // [layer][16 groups * 32 pad]

__device__ __forceinline__ unsigned long long ffma2(unsigned long long a,
                                                    unsigned long long b,
                                                    unsigned long long c) {
    unsigned long long d;
    asm("fma.rn.f32x2 %0,%1,%2,%3;" : "=l"(d) : "l"(a), "l"(b), "l"(c));
    return d;
}
__device__ __forceinline__ unsigned long long dup2(float x) {
    unsigned long long d;
    asm("mov.b64 %0,{%1,%1};" : "=l"(d) : "r"(__float_as_uint(x)));
    return d;
}
union F4U { float4 v; float f[4]; unsigned long long u[2]; };

__device__ __forceinline__ void red_release_gpu(unsigned* p, unsigned v) {
    asm volatile("red.release.gpu.global.add.u32 [%0], %1;" :: "l"(p), "r"(v) : "memory");
}
__device__ __forceinline__ unsigned ld_acquire_gpu(const unsigned* p) {
    unsigned v;
    asm volatile("ld.acquire.gpu.global.u32 %0, [%1];" : "=r"(v) : "l"(p) : "memory");
    return v;
}

// inf-safe fast activations (MUFU ex2/rcp based)
__device__ __forceinline__ float fsig(float x) {
    return __fdividef(1.0f, 1.0f + __expf(-x));
}
__device__ __forceinline__ float ftanh(float x) {
    return 1.0f - __fdividef(2.0f, 1.0f + __expf(2.0f * x));
}

// ================= GEMM: 2-stage register-prefetch pipeline =================
#define BM 128
#define BN 128
#define BK 8

__global__ __launch_bounds__(256, 2)
void gemm_kernel(int mode, const int* __restrict__ gidx, const float* __restrict__ emb,
                 const float* __restrict__ Wf, const float* __restrict__ Wb,
                 const float* __restrict__ bf, const float* __restrict__ bb,
                 int K, int czoff)
{
    const int tid = threadIdx.x;
    if (blockIdx.x == 0 && blockIdx.y == 0 && blockIdx.z == 0) {   // reset rec barrier bank
        g_cnt[czoff + tid] = 0u; g_cnt[czoff + 256 + tid] = 0u;
    }
    const int dir = blockIdx.z;
    const float* __restrict__ W    = dir ? Wb : Wf;
    const float* __restrict__ bias = dir ? bb : bf;
    float* outp = g_xw + (size_t)dir * NB * TLEN * GDIM;
    const int bm = blockIdx.y * BM, bn = blockIdx.x * BN;

    __shared__ float As[BK][BM + 4];
    __shared__ float Bs[BK][BN];

    const int a_m = tid >> 1, a_k = (tid & 1) * 4;
    const int b_k = tid >> 5, b_n = (tid & 31) * 4;
    const int tx = tid & 15, ty = tid >> 4;

    const float* arow = mode ? (g_h1 + (size_t)(bm + a_m) * (2 * UDIM))
                             : (emb + (size_t)gidx[bm + a_m] * EDIM);

    auto loadA = [&](int k0, F4U& a) {
        if (k0 + a_k + 4 <= K) {
            a.v = *(const float4*)(arow + k0 + a_k);
        } else {
#pragma unroll
            for (int i = 0; i < 4; i++) {
                int kk = k0 + a_k + i;
                a.f[i] = (kk < K) ? arow[kk] : 0.0f;
            }
        }
    };
    auto loadB = [&](int k0, F4U& b) {
        int kk = k0 + b_k;
        b.v = make_float4(0.f, 0.f, 0.f, 0.f);
        if (kk < K) b.v = *(const float4*)(W + (size_t)kk * GDIM + bn + b_n);
    };
    auto stsTile = [&](const F4U& a, const F4U& b) {
        As[a_k + 0][a_m] = a.f[0]; As[a_k + 1][a_m] = a.f[1];
        As[a_k + 2][a_m] = a.f[2]; As[a_k + 3][a_m] = a.f[3];
        *(float4*)&Bs[b_k][b_n] = b.v;
    };

    unsigned long long acc[8][4];
#pragma unroll
    for (int i = 0; i < 8; i++)
#pragma unroll
        for (int j = 0; j < 4; j++) acc[i][j] = 0ull;

    {
        F4U a0, b0;
        loadA(0, a0); loadB(0, b0);
        stsTile(a0, b0);
    }
    __syncthreads();

    int k0 = 0;
    for (;;) {
        const int k1 = k0 + BK;
        const bool more = (k1 < K);
        F4U anx, bnx;
        if (more) { loadA(k1, anx); loadB(k1, bnx); }   // prefetch next (hidden)

#pragma unroll
        for (int kk = 0; kk < BK; kk++) {
            F4U a0, a1, b0, b1;
            a0.v = *(const float4*)&As[kk][ty * 4];
            a1.v = *(const float4*)&As[kk][64 + ty * 4];
            b0.v = *(const float4*)&Bs[kk][tx * 4];
            b1.v = *(const float4*)&Bs[kk][64 + tx * 4];
            unsigned long long ap[8];
            unsigned long long bp[4] = { b0.u[0], b0.u[1], b1.u[0], b1.u[1] };
#pragma unroll
            for (int i = 0; i < 4; i++) { ap[i] = dup2(a0.f[i]); ap[4 + i] = dup2(a1.f[i]); }
#pragma unroll
            for (int i = 0; i < 8; i++)
#pragma unroll
                for (int j = 0; j < 4; j++)
                    acc[i][j] = ffma2(ap[i], bp[j], acc[i][j]);
        }
        if (!more) break;
        __syncthreads();
        stsTile(anx, bnx);
        __syncthreads();
        k0 = k1;
    }

#pragma unroll
    for (int i = 0; i < 8; i++) {
        int m = bm + ((i < 4) ? (ty * 4 + i) : (64 + ty * 4 + i - 4));
        float* orow = outp + (size_t)m * GDIM + bn;
#pragma unroll
        for (int j = 0; j < 4; j++) {
            int c = (j < 2) ? (tx * 4 + j * 2) : (64 + tx * 4 + (j - 2) * 2);
            F4U t; t.u[0] = acc[i][j];
            float2 r;
            r.x = t.f[0] + bias[bn + c];
            r.y = t.f[1] + bias[bn + c + 1];
            *(float2*)(orow + c) = r;
        }
    }
}

// ===== Recurrence v6: R12 tail + hprev regs + per-warp quadrant reload =====
// 128 CTAs = dir(2) x batch-group(8) x unit-slice(8).
// 256 threads = kq(4 k-quarters) x bq(2 batch-quads) x unit(32).
// Per step: reload own slice (warp-private) -> matvec -> partials -> BAR1 ->
// kq0: reduce+gates(hprev regs)+STG -> bar.sync(1,64) -> tid0 release+poll
// (g_h1/g_h2 stores overlap) -> BAR2 -> per-warp __ldcg reload, NO final BAR.
#define RED_F (3 * 2 * 32 * 12)
#define REC_SMEM ((96 * KP + 8 * 256 + RED_F) * 4)

__global__ __launch_bounds__(256, 1)
void rec_kernel(const float* __restrict__ rkf, const float* __restrict__ rkb,
                const float* __restrict__ rbf, const float* __restrict__ rbb,
                int layer, int coff)
{
    extern __shared__ float sm[];
    float* rk_s = sm;                       // [96][KP]
    float* h_s  = sm + 96 * KP;             // [8][256]
    float* red  = h_s + 8 * 256;            // [3][2][32][12]
    const int blk = blockIdx.x, dir = blk >> 6, bg = (blk >> 3) & 7, us = blk & 7;
    const int tid = threadIdx.x;
    const int kq = tid >> 6, bq = (tid >> 5) & 1, j = tid & 31;
    const float* __restrict__ rk = dir ? rkb : rkf;
    const float* __restrict__ rb = dir ? rbb : rbf;

    for (int i = tid; i < 96 * 256; i += 256) {
        int k = i / 96, c = i - k * 96;
        rk_s[c * KP + k] = rk[(size_t)k * GDIM + (c >> 5) * UDIM + us * 32 + (c & 31)];
    }
    for (int i = tid; i < 8 * 256; i += 256) h_s[i] = 0.0f;
    __syncthreads();

    const int u = us * 32 + j;
    const int kb = kq * 64;
    const float rbz = rb[u], rbr = rb[UDIM + u], rbh = rb[2 * UDIM + u];
    const float* xwd = g_xw + (size_t)dir * NB * TLEN * GDIM;
    unsigned* cp = g_cnt + coff + (dir * 8 + bg) * 32;
    const float* rzp = rk_s + (size_t)j * KP + kb;
    const float* rrp = rk_s + (size_t)(32 + j) * KP + kb;
    const float* rhp = rk_s + (size_t)(64 + j) * KP + kb;
    const float* hpb = h_s + (bq * 4) * 256 + kb;

    float* gb0 = g_hbuf + ((0 * 2 + dir) * 8 + bg) * (8 * UDIM);
    float* gb1 = g_hbuf + ((1 * 2 + dir) * 8 + bg) * (8 * UDIM);

    // per-warp reload slice: the 64 float4 this warp's matvec reads
    // (batches bq*4+(j>>4), +2 ; k-quarter kq), same f4 index in h_s and gb.
    const int qi0 = (bq * 4 + (j >> 4)) * 64 + kq * 16 + (j & 15);
    const int qi1 = qi0 + 2 * 64;

    float hprev[4] = {0.f, 0.f, 0.f, 0.f};   // kq0 warps: own-unit h state

    for (int s = 0; s < TLEN; s++) {
        const int t = dir ? (TLEN - 1 - s) : s;

        float xz[4], xr[4], xh[4];
        if (kq == 0) {
#pragma unroll
            for (int i = 0; i < 4; i++) {
                const float* xr0 = xwd + ((size_t)(bg * 8 + bq * 4 + i) * TLEN + t) * GDIM;
                xz[i] = __ldg(xr0 + u);
                xr[i] = __ldg(xr0 + UDIM + u);
                xh[i] = __ldg(xr0 + 2 * UDIM + u);
            }
        }

        unsigned long long az[4], ar[4], ah[4];
#pragma unroll
        for (int i = 0; i < 4; i++) { az[i] = 0ull; ar[i] = 0ull; ah[i] = 0ull; }

#pragma unroll 4
        for (int k = 0; k < 64; k += 4) {
            F4U vz, vr, vh;
            vz.v = *(const float4*)(rzp + k);
            vr.v = *(const float4*)(rrp + k);
            vh.v = *(const float4*)(rhp + k);
#pragma unroll
            for (int i = 0; i < 4; i++) {
                F4U hv; hv.v = *(const float4*)(hpb + i * 256 + k);
                az[i] = ffma2(vz.u[0], hv.u[0], az[i]);
                az[i] = ffma2(vz.u[1], hv.u[1], az[i]);
                ar[i] = ffma2(vr.u[0], hv.u[0], ar[i]);
                ar[i] = ffma2(vr.u[1], hv.u[1], ar[i]);
                ah[i] = ffma2(vh.u[0], hv.u[0], ah[i]);
                ah[i] = ffma2(vh.u[1], hv.u[1], ah[i]);
            }
        }

        float sz[4], sr[4], sh[4];
#pragma unroll
        for (int i = 0; i < 4; i++) {
            F4U a; a.u[0] = az[i]; sz[i] = a.f[0] + a.f[1];
            a.u[0] = ar[i];        sr[i] = a.f[0] + a.f[1];
            a.u[0] = ah[i];        sh[i] = a.f[0] + a.f[1];
        }

        if (kq != 0) {
            float* rp = red + (((kq - 1) * 2 + bq) * 32 + j) * 12;
            *(float4*)(rp + 0) = make_float4(sz[0], sz[1], sz[2], sz[3]);
            *(float4*)(rp + 4) = make_float4(sr[0], sr[1], sr[2], sr[3]);
            *(float4*)(rp + 8) = make_float4(sh[0], sh[1], sh[2], sh[3]);
        }
        __syncthreads();   // BAR1: partials visible to kq0

        float hn[4];
        if (kq == 0) {
#pragma unroll
            for (int q = 0; q < 3; q++) {
                const float* rp = red + ((q * 2 + bq) * 32 + j) * 12;
                float4 a = *(const float4*)(rp + 0);
                float4 b = *(const float4*)(rp + 4);
                float4 c = *(const float4*)(rp + 8);
                sz[0] += a.x; sz[1] += a.y; sz[2] += a.z; sz[3] += a.w;
                sr[0] += b.x; sr[1] += b.y; sr[2] += b.z; sr[3] += b.w;
                sh[0] += c.x; sh[1] += c.y; sh[2] += c.z; sh[3] += c.w;
            }
            float* gb = (s & 1) ? gb1 : gb0;
#pragma unroll
            for (int i = 0; i < 4; i++) {
                const int bL = bq * 4 + i;
                float z = fsig(xz[i] + rbz + sz[i]);
                float r = fsig(xr[i] + rbr + sr[i]);
                float hh = ftanh(xh[i] + rbh + r * sh[i]);
                hn[i] = z * hprev[i] + (1.f - z) * hh;
                hprev[i] = hn[i];
                gb[bL * UDIM + u] = hn[i];       // exchanged state only
            }
            // only warps 0,1 (kq0) produced gb STGs; sync them before release
            asm volatile("bar.sync 1, 64;" ::: "memory");
            if (tid == 0) {
                red_release_gpu(cp, 1u);
                const unsigned tgt = 8u * (unsigned)(s + 1);
                while (ld_acquire_gpu(cp) < tgt) __nanosleep(64);
            }
            // off-path global stores (read only by later launches): overlap poll
            if (layer == 1) {
#pragma unroll
                for (int i = 0; i < 4; i++) {
                    const int Bg = bg * 8 + bq * 4 + i;
                    g_h1[((size_t)Bg * TLEN + t) * (2 * UDIM) + dir * UDIM + u] = hn[i];
                }
            } else if (s == TLEN - 1) {
#pragma unroll
                for (int i = 0; i < 4; i++) {
                    const int Bg = bg * 8 + bq * 4 + i;
                    g_h2[Bg * 2 * UDIM + dir * UDIM + u] = hn[i];
                }
            }
        }
        __syncthreads();   // BAR2: tid0's acquire -> peer hn visible to all warps

        // per-warp reload of exactly this warp's matvec slice; h_s regions are
        // warp-disjoint and gates use hprev regs -> no trailing barrier needed.
        {
            const float4* src = (const float4*)((s & 1) ? gb1 : gb0);
            float4* dst = (float4*)h_s;
            dst[qi0] = __ldcg(src + qi0);
            dst[qi1] = __ldcg(src + qi1);
        }
    }
}

// ======================== softmax head =================================
__global__ void out_kernel(const float* __restrict__ wout, const float* __restrict__ bout,
                           float* __restrict__ out)
{
    __shared__ float h[2 * UDIM];
    const int b = blockIdx.x, t = threadIdx.x;
    for (int i = t; i < 128; i += 32)
        ((float4*)h)[i] = ((const float4*)(g_h2 + b * 2 * UDIM))[i];
    __syncwarp();
    float l = -1e30f;
    if (t < CDIM) {
        float a = bout[t];
        for (int k = 0; k < 2 * UDIM; k++) a = fmaf(h[k], wout[k * CDIM + t], a);
        l = a;
    }
    float m = l;
    for (int o = 16; o; o >>= 1) m = fmaxf(m, __shfl_xor_sync(~0u, m, o));
    float e = (t < CDIM) ? expf(l - m) : 0.0f, ssum = e;
    for (int o = 16; o; o >>= 1) ssum += __shfl_xor_sync(~0u, ssum, o);
    if (t < CDIM) out[b * CDIM + t] = e / ssum;
}

// ========================= launcher ====================================
extern "C" void kernel_launch(void* const* d_in, const int* in_sizes, int n_in,
                              void* d_out, int out_size)
{
    const int*   x    = (const int*)d_in[0];
    const float* emb  = (const float*)d_in[1];
    const float* k1f  = (const float*)d_in[2];
    const float* rk1f = (const float*)d_in[3];
    const float* b1f  = (const float*)d_in[4];
    const float* k1b  = (const float*)d_in[5];
    const float* rk1b = (const float*)d_in[6];
    const float* b1b  = (const float*)d_in[7];
    const float* k2f  = (const float*)d_in[8];
    const float* rk2f = (const float*)d_in[9];
    const float* b2f  = (const float*)d_in[10];
    const float* k2b  = (const float*)d_in[11];
    const float* rk2b = (const float*)d_in[12];
    const float* b2b  = (const float*)d_in[13];
    const float* wout = (const float*)d_in[14];
    const float* bout = (const float*)d_in[15];
    float* out = (float*)d_out;
    (void)in_sizes; (void)n_in; (void)out_size;

    cudaFuncSetAttribute(rec_kernel, cudaFuncAttributeMaxDynamicSharedMemorySize, REC_SMEM);

    dim3 gg(GDIM / BN, (NB * TLEN) / BM, 2);
    gemm_kernel<<<gg, 256>>>(0, x, emb, k1f, k1b, b1f, b1b, EDIM, 0);
    rec_kernel<<<128, 256, REC_SMEM>>>(rk1f, rk1b, b1f + GDIM, b1b + GDIM, 1, 0);
    gemm_kernel<<<gg, 256>>>(1, x, emb, k2f, k2b, b2f, b2b, 2 * UDIM, 512);
    rec_kernel<<<128, 256, REC_SMEM>>>(rk2f, rk2b, b2f + GDIM, b2b + GDIM, 2, 512);
    out_kernel<<<NB, 32>>>(wout, bout, out);
}